// round 12
// baseline (speedup 1.0000x reference)
#include <cuda_runtime.h>
#include <cuda_bf16.h>
#include <math.h>
#include <stdint.h>

// ---------------- problem constants ----------------
#define L_TOK   131040          // 8*91*180
#define TOKW    138240          // 960 windows * 144 tokens
#define DIMC    192
#define HID     768
#define NHEAD   6
#define HDIM    32
#define NTOK    144             // tokens per window (2*6*12)
#define NWIN    64              // windows per lon-group (4*16)
#define NLON    15
#define BWN     960             // NLON*NWIN
#define BROWS   3312            // bias table rows: 4*36*23

// GEMM tiling (SW128 swizzled smem, BM=128, BK=64, 512 threads, 16 warps 4x4)
#define BM 128
#define BN 192
#define BK 64
#define GSTAGES 3
#define ASTG (BM * 128)                  // 16384 B
#define BSTG (BN * 128)                  // 24576 B
#define STGB (ASTG + BSTG)               // 40960 B
#define GEMM_SMEM (STGB * GSTAGES)       // 122880 B

// attention smem layout
#define APAD 40                          // row stride in halves for q/k/v
#define MATH (NTOK * APAD)               // 5760 halves per matrix
#define MATB (MATH * 2)                  // 11520 bytes
#define STAGEB (3 * MATB)                // 34560 bytes per stage
#define PADB 146                         // bias row stride (halves)
#define BIASB (NTOK * PADB * 2)          // 42048 bytes
#define ATTN_SMEM (2 * STAGEB + BIASB + 2 * NTOK * 4)   // 112320

// ---------------- scratch buffers ----------------
__device__ __nv_bfloat16 g_A1[(size_t)TOKW * DIMC];
__device__ __nv_bfloat16 g_qkv[(size_t)TOKW * 3 * DIMC];
__device__ float         g_btabT[(size_t)NWIN * NHEAD * BROWS];   // [b2][bidx]
__device__ __nv_bfloat16 g_attnout[(size_t)TOKW * DIMC];
__device__ __nv_bfloat16 g_projout[(size_t)TOKW * DIMC];
__device__ float         g_x1[(size_t)L_TOK * DIMC];
__device__ __nv_bfloat16 g_h2in[(size_t)L_TOK * DIMC];
__device__ __nv_bfloat16 g_h2mid[(size_t)L_TOK * HID];
__device__ __nv_bfloat16 g_wqkv[3 * DIMC * DIMC];
__device__ __nv_bfloat16 g_wproj[DIMC * DIMC];
__device__ __nv_bfloat16 g_wfc1[HID * DIMC];
__device__ __nv_bfloat16 g_wfc2[DIMC * HID];

// ---------------- helpers ----------------
__device__ __forceinline__ void cp_async16(uint32_t saddr, const void* gptr, bool pred) {
    int sz = pred ? 16 : 0;
    asm volatile("cp.async.cg.shared.global [%0], [%1], 16, %2;\n"
                 :: "r"(saddr), "l"(gptr), "r"(sz));
}

__device__ __forceinline__ void ldsm4(uint32_t* r, uint32_t addr) {
    asm volatile("ldmatrix.sync.aligned.m8n8.x4.shared.b16 {%0,%1,%2,%3}, [%4];\n"
                 : "=r"(r[0]), "=r"(r[1]), "=r"(r[2]), "=r"(r[3]) : "r"(addr));
}

__device__ __forceinline__ void ldsm4t(uint32_t* r, uint32_t addr) {
    asm volatile("ldmatrix.sync.aligned.m8n8.x4.trans.shared.b16 {%0,%1,%2,%3}, [%4];\n"
                 : "=r"(r[0]), "=r"(r[1]), "=r"(r[2]), "=r"(r[3]) : "r"(addr));
}

__device__ __forceinline__ void mma16816(float* d, const uint32_t* a, const uint32_t* b) {
    asm volatile(
        "mma.sync.aligned.m16n8k16.row.col.f32.bf16.bf16.f32 "
        "{%0,%1,%2,%3}, {%4,%5,%6,%7}, {%8,%9}, {%0,%1,%2,%3};\n"
        : "+f"(d[0]), "+f"(d[1]), "+f"(d[2]), "+f"(d[3])
        : "r"(a[0]), "r"(a[1]), "r"(a[2]), "r"(a[3]), "r"(b[0]), "r"(b[1]));
}

__device__ __forceinline__ uint32_t packbf2(float lo, float hi) {
    __nv_bfloat162 p = __nv_bfloat162(__float2bfloat16(lo), __float2bfloat16(hi));
    return *reinterpret_cast<uint32_t*>(&p);
}

// ---------------- merged weight conversion ----------------
__global__ __launch_bounds__(256) void wconv_kernel(
    const float* __restrict__ s0, const float* __restrict__ s1,
    const float* __restrict__ s2, const float* __restrict__ s3) {
    int i = blockIdx.x * 256 + threadIdx.x;
    if (i < 110592)      g_wqkv[i]  = __float2bfloat16(s0[i]);
    else if (i < 147456) { int j = i - 110592;  g_wproj[j] = __float2bfloat16(s1[j]); }
    else if (i < 294912) { int j = i - 147456;  g_wfc1[j]  = __float2bfloat16(s2[j]); }
    else if (i < 442368) { int j = i - 294912;  g_wfc2[j]  = __float2bfloat16(s3[j]); }
}

// ---------------- bias table transpose: [bidx][b2] -> [b2][bidx] ----------------
__global__ __launch_bounds__(256) void btab_t_kernel(const float* __restrict__ btab) {
    int e = blockIdx.x * 256 + threadIdx.x;
    if (e < BROWS * NWIN * NHEAD) {
        int b2 = e / BROWS, bidx = e - b2 * BROWS;
        g_btabT[e] = btab[(size_t)bidx * (NWIN * NHEAD) + b2];
    }
}

// ---------------- LN1 + pad + roll + window partition (warp per token) ----------------
__global__ __launch_bounds__(256) void ln1_window_kernel(const float* __restrict__ x,
                                                          const float* __restrict__ w,
                                                          const float* __restrict__ b) {
    int t = blockIdx.x * 8 + (threadIdx.x >> 5);
    int lane = threadIdx.x & 31;
    int bw = t / NTOK, n = t - bw * NTOK;
    int li = bw >> 6, wdw = bw & 63;
    int wp_i = n / 72, wa_i = (n / 12) % 6, wo_i = n % 12;
    int pl_p  = (wdw >> 4) * 2 + wp_i;
    int lat_p = (wdw & 15) * 6 + wa_i;
    int lon_p = li * 12 + wo_i;
    int pl_s  = (pl_p + 1) & 7;
    int lat_s = (lat_p + 3) % 96;
    int lon_s = (lon_p + 6) % 180;
    int lat_o = lat_s - 2;
    bool valid = (lat_o >= 0) && (lat_o < 91);
    size_t src = valid ? ((size_t)(pl_s * 91 + lat_o) * 180 + lon_s) * DIMC : 0;
    float v[6]; float s = 0.f, s2 = 0.f;
    #pragma unroll
    for (int k = 0; k < 6; k++) {
        float vv = valid ? x[src + lane + 32 * k] : 0.f;
        v[k] = vv; s += vv; s2 += vv * vv;
    }
    #pragma unroll
    for (int o = 16; o > 0; o >>= 1) {
        s  += __shfl_xor_sync(0xffffffffu, s, o);
        s2 += __shfl_xor_sync(0xffffffffu, s2, o);
    }
    float mean = s * (1.f / 192.f);
    float var  = s2 * (1.f / 192.f) - mean * mean;
    float rstd = rsqrtf(var + 1e-5f);
    #pragma unroll
    for (int k = 0; k < 6; k++) {
        int c = lane + 32 * k;
        float h = valid ? (v[k] - mean) * rstd * w[c] + b[c] : 0.f;
        g_A1[(size_t)t * DIMC + c] = __float2bfloat16(h);
    }
}

// ---------------- bf16 GEMM: BM=128, BK=64, SW128, 512 thr, 16 warps 4x4, tile 32x48 ----
// MODE 1: bf16 out + bias   MODE 2: gelu(acc+bias) -> bf16   MODE 3: Out = X1 + acc + bias (fp32)
template <int MODE>
__global__ __launch_bounds__(512, 1) void gemm2(
    int M, int N, int K,
    const __nv_bfloat16* __restrict__ A,
    const __nv_bfloat16* __restrict__ Bw,
    const float* __restrict__ bias,
    __nv_bfloat16* __restrict__ Cb,
    const float* __restrict__ X1,
    float* __restrict__ Out) {
    extern __shared__ __align__(16) unsigned char smraw[];
    uint32_t smem_u32 = (uint32_t)__cvta_generic_to_shared(smraw);

    const int tid = threadIdx.x;
    const int lane = tid & 31, warp = tid >> 5;   // warp 0..15
    const int m0 = blockIdx.y * BM;
    const int n0 = blockIdx.x * BN;
    const int wm = (warp >> 2) * 32;   // 4 warp rows * 32
    const int wn = (warp & 3) * 48;    // 4 warp cols * 48
    const int KT = K >> 6;             // k-chunks of 64

    float acc[2][6][4];
    #pragma unroll
    for (int a = 0; a < 2; a++)
        #pragma unroll
        for (int b2 = 0; b2 < 6; b2++)
            #pragma unroll
            for (int c = 0; c < 4; c++) acc[a][b2][c] = 0.f;

    // swizzled stage load: row has 8 x 16B chunks; physical chunk = c ^ (row & 7)
    auto load_stage = [&](int stage, int kt) {
        const int kb = kt << 6;
        uint32_t abase = smem_u32 + stage * STGB;
        #pragma unroll
        for (int it = 0; it < 2; it++) {   // A: 128 rows * 8 chunks = 1024
            int q = tid + it * 512;
            int row = q >> 3, c = q & 7;
            int gr = m0 + row;
            bool p = gr < M;
            const __nv_bfloat16* gp = A + (size_t)(p ? gr : 0) * K + kb + c * 8;
            cp_async16(abase + (uint32_t)(row * 128 + ((c ^ (row & 7)) << 4)), gp, p);
        }
        uint32_t bbase = abase + ASTG;
        #pragma unroll
        for (int it = 0; it < 3; it++) {   // B: 192 rows * 8 chunks = 1536
            int q = tid + it * 512;
            int row = q >> 3, c = q & 7;
            const __nv_bfloat16* gp = Bw + (size_t)(n0 + row) * K + kb + c * 8;
            cp_async16(bbase + (uint32_t)(row * 128 + ((c ^ (row & 7)) << 4)), gp, true);
        }
    };

    #pragma unroll
    for (int s = 0; s < GSTAGES - 1; s++) {
        load_stage(s, s);
        asm volatile("cp.async.commit_group;\n");
    }

    for (int kt = 0; kt < KT; kt++) {
        asm volatile("cp.async.wait_group 1;\n");
        __syncthreads();
        int kn = kt + GSTAGES - 1;
        if (kn < KT) load_stage(kn % GSTAGES, kn);
        asm volatile("cp.async.commit_group;\n");

        uint32_t abase = smem_u32 + (kt % GSTAGES) * STGB;
        uint32_t bbase = abase + ASTG;
        #pragma unroll
        for (int t = 0; t < 4; t++) {      // 4 k16 steps inside the 64-chunk
            uint32_t af[2][4], bfr[3][4];
            #pragma unroll
            for (int mi = 0; mi < 2; mi++) {
                int r = wm + mi * 16 + (lane & 15);
                int c = 2 * t + ((lane & 16) >> 4);
                ldsm4(af[mi], abase + (uint32_t)(r * 128 + ((c ^ (r & 7)) << 4)));
            }
            #pragma unroll
            for (int nb = 0; nb < 3; nb++) {
                int r = wn + nb * 16 + (lane & 7) + ((lane & 16) >> 1);
                int c = 2 * t + ((lane & 8) >> 3);
                ldsm4(bfr[nb], bbase + (uint32_t)(r * 128 + ((c ^ (r & 7)) << 4)));
            }
            #pragma unroll
            for (int mi = 0; mi < 2; mi++)
                #pragma unroll
                for (int ni = 0; ni < 6; ni++)
                    mma16816(acc[mi][ni], af[mi], &bfr[ni >> 1][(ni & 1) * 2]);
        }
    }

    // epilogue
    const int g = lane >> 2, c4 = lane & 3;
    #pragma unroll
    for (int mi = 0; mi < 2; mi++) {
        #pragma unroll
        for (int ni = 0; ni < 6; ni++) {
            int row0 = m0 + wm + mi * 16 + g;
            int col0 = n0 + wn + ni * 8 + 2 * c4;
            float2 bv = *(const float2*)(bias + col0);
            #pragma unroll
            for (int rr = 0; rr < 2; rr++) {
                int row = row0 + rr * 8;
                if (row >= M) continue;
                float v0 = acc[mi][ni][rr * 2 + 0] + bv.x;
                float v1 = acc[mi][ni][rr * 2 + 1] + bv.y;
                size_t off = (size_t)row * N + col0;
                if (MODE == 1) {
                    *(__nv_bfloat162*)(Cb + off) =
                        __nv_bfloat162(__float2bfloat16(v0), __float2bfloat16(v1));
                } else if (MODE == 2) {
                    float g0 = 0.5f * v0 * (1.0f + erff(v0 * 0.70710678118654752f));
                    float g1 = 0.5f * v1 * (1.0f + erff(v1 * 0.70710678118654752f));
                    *(__nv_bfloat162*)(Cb + off) =
                        __nv_bfloat162(__float2bfloat16(g0), __float2bfloat16(g1));
                } else {
                    float2 xv = *(const float2*)(X1 + off);
                    *(float2*)(Out + off) = make_float2(xv.x + v0, xv.y + v1);
                }
            }
        }
    }
}

// ---------------- tensor-core windowed attention, bias reused across 15 lon-groups ----------
// block = (head, wdw); 9 warps; loop li=0..14 with double-buffered cp.async qkv staging.
__global__ __launch_bounds__(288, 1) void attn_kernel() {
    const int head = blockIdx.x;
    const int wdw = blockIdx.y;
    const int tid = threadIdx.x;
    const int lane = tid & 31;
    const int warp = tid >> 5;

    extern __shared__ __align__(16) unsigned char smraw[];
    __nv_bfloat16* sbias = (__nv_bfloat16*)(smraw + 2 * STAGEB);
    int* sid0  = (int*)(smraw + 2 * STAGEB + BIASB);
    int* sid14 = sid0 + NTOK;
    uint32_t squ = (uint32_t)__cvta_generic_to_shared(smraw);

    auto load_st = [&](int st, int li) {
        int bw = li * NWIN + wdw;
        const __nv_bfloat16* gb = g_qkv + (size_t)bw * NTOK * (3 * DIMC) + head * HDIM;
        uint32_t sb = squ + st * STAGEB;
        #pragma unroll
        for (int s = 0; s < 6; s++) {
            int c = tid + s * 288;
            int mat = c / 576, rem = c - mat * 576, j = rem >> 2, q16 = rem & 3;
            const void* gp = gb + (size_t)j * (3 * DIMC) + mat * DIMC + q16 * 8;
            cp_async16(sb + (uint32_t)(mat * MATB + j * (APAD * 2) + q16 * 16), gp, true);
        }
    };

    load_st(0, 0);
    asm volatile("cp.async.commit_group;\n");

    if (tid < NTOK) {
        int n = tid;
        int wp_i = n / 72, wa_i = (n / 12) % 6, wo_i = n % 12;
        int pl_p  = (wdw >> 4) * 2 + wp_i;
        int lat_p = (wdw & 15) * 6 + wa_i;
        int rpl  = pl_p  < 6  ? 0 : (pl_p  < 7  ? 1 : 2);
        int rlat = lat_p < 90 ? 0 : (lat_p < 93 ? 1 : 2);
        int base = (rpl * 3 + rlat) * 3;
        sid0[n]  = base;
        sid14[n] = base + ((168 + wo_i) >= 174 ? 1 : 0);
    }
    {
        const float* bt = g_btabT + (size_t)(wdw * NHEAD + head) * BROWS;
        for (int e = tid; e < NTOK * NTOK; e += 288) {
            int i = e / NTOK, j = e - i * NTOK;
            int zi = i / 72, hi = (i / 12) % 6, wi = i % 12;
            int zj = j / 72, hj = (j / 12) % 6, wj = j % 12;
            int bidx = (zi + 2 * zj) * 828 + (hi + 6 * hj) * 23 + (wi - wj + 11);
            sbias[i * PADB + j] = __float2bfloat16(bt[bidx]);
        }
    }

    const int qrow0 = warp * 16;
    const int g = lane >> 2, c4 = lane & 3;
    const int row0 = qrow0 + g, row1 = row0 + 8;
    const float qscale = 0.17677669529663687f;

    for (int li = 0; li < NLON; li++) {
        if (li + 1 < NLON) {
            load_st((li + 1) & 1, li + 1);
            asm volatile("cp.async.commit_group;\n");
            asm volatile("cp.async.wait_group 1;\n");
        } else {
            asm volatile("cp.async.wait_group 0;\n");
        }
        __syncthreads();

        uint32_t sq_b = squ + (li & 1) * STAGEB;
        uint32_t sk_b = sq_b + MATB;
        uint32_t sv_b = sk_b + MATB;
        const int* sregp = (li == 14) ? sid14 : sid0;

        uint32_t aq[2][4];
        #pragma unroll
        for (int kkidx = 0; kkidx < 2; kkidx++) {
            uint32_t addr = sq_b + (uint32_t)((qrow0 + (lane & 15)) * (APAD * 2)
                                              + kkidx * 32 + (lane & 16));
            ldsm4(aq[kkidx], addr);
        }

        float sacc[18][4];
        #pragma unroll
        for (int t = 0; t < 18; t++)
            #pragma unroll
            for (int c = 0; c < 4; c++) sacc[t][c] = 0.f;

        #pragma unroll
        for (int nt = 0; nt < 9; nt++) {
            #pragma unroll
            for (int kkidx = 0; kkidx < 2; kkidx++) {
                uint32_t bk[4];
                uint32_t addr = sk_b +
                    (uint32_t)((nt * 16 + (lane & 7) + ((lane & 16) >> 1)) * (APAD * 2)
                               + kkidx * 32 + (lane & 8) * 2);
                ldsm4(bk, addr);
                mma16816(sacc[2 * nt],     aq[kkidx], &bk[0]);
                mma16816(sacc[2 * nt + 1], aq[kkidx], &bk[2]);
            }
        }

        const int rg0 = sregp[row0], rg1 = sregp[row1];
        #pragma unroll
        for (int t = 0; t < 18; t++) {
            int col = t * 8 + 2 * c4;
            float2 b0 = __bfloat1622float2(*(const __nv_bfloat162*)(sbias + row0 * PADB + col));
            float2 b1 = __bfloat1622float2(*(const __nv_bfloat162*)(sbias + row1 * PADB + col));
            int rc0 = sregp[col], rc1 = sregp[col + 1];
            sacc[t][0] = fmaf(sacc[t][0], qscale, b0.x + (rc0 != rg0 ? -100.f : 0.f));
            sacc[t][1] = fmaf(sacc[t][1], qscale, b0.y + (rc1 != rg0 ? -100.f : 0.f));
            sacc[t][2] = fmaf(sacc[t][2], qscale, b1.x + (rc0 != rg1 ? -100.f : 0.f));
            sacc[t][3] = fmaf(sacc[t][3], qscale, b1.y + (rc1 != rg1 ? -100.f : 0.f));
        }

        float mx0 = -1e30f, mx1 = -1e30f;
        #pragma unroll
        for (int t = 0; t < 18; t++) {
            mx0 = fmaxf(mx0, fmaxf(sacc[t][0], sacc[t][1]));
            mx1 = fmaxf(mx1, fmaxf(sacc[t][2], sacc[t][3]));
        }
        #pragma unroll
        for (int o = 1; o <= 2; o <<= 1) {
            mx0 = fmaxf(mx0, __shfl_xor_sync(0xffffffffu, mx0, o));
            mx1 = fmaxf(mx1, __shfl_xor_sync(0xffffffffu, mx1, o));
        }
        float sum0 = 0.f, sum1 = 0.f;
        #pragma unroll
        for (int t = 0; t < 18; t++) {
            sacc[t][0] = __expf(sacc[t][0] - mx0);
            sacc[t][1] = __expf(sacc[t][1] - mx0);
            sacc[t][2] = __expf(sacc[t][2] - mx1);
            sacc[t][3] = __expf(sacc[t][3] - mx1);
            sum0 += sacc[t][0] + sacc[t][1];
            sum1 += sacc[t][2] + sacc[t][3];
        }
        #pragma unroll
        for (int o = 1; o <= 2; o <<= 1) {
            sum0 += __shfl_xor_sync(0xffffffffu, sum0, o);
            sum1 += __shfl_xor_sync(0xffffffffu, sum1, o);
        }
        float inv0 = 1.f / sum0, inv1 = 1.f / sum1;

        uint32_t ap[9][4];
        #pragma unroll
        for (int kt = 0; kt < 9; kt++) {
            ap[kt][0] = packbf2(sacc[2 * kt][0],     sacc[2 * kt][1]);
            ap[kt][1] = packbf2(sacc[2 * kt][2],     sacc[2 * kt][3]);
            ap[kt][2] = packbf2(sacc[2 * kt + 1][0], sacc[2 * kt + 1][1]);
            ap[kt][3] = packbf2(sacc[2 * kt + 1][2], sacc[2 * kt + 1][3]);
        }

        float oacc[4][4];
        #pragma unroll
        for (int t = 0; t < 4; t++)
            #pragma unroll
            for (int c = 0; c < 4; c++) oacc[t][c] = 0.f;

        #pragma unroll
        for (int kt = 0; kt < 9; kt++) {
            #pragma unroll
            for (int dh = 0; dh < 2; dh++) {
                uint32_t bv[4];
                uint32_t addr = sv_b +
                    (uint32_t)((kt * 16 + (lane & 15)) * (APAD * 2) + dh * 32 + (lane & 16));
                ldsm4t(bv, addr);
                mma16816(oacc[2 * dh],     ap[kt], &bv[0]);
                mma16816(oacc[2 * dh + 1], ap[kt], &bv[2]);
            }
        }

        int bw = li * NWIN + wdw;
        #pragma unroll
        for (int dt = 0; dt < 4; dt++) {
            int col = head * HDIM + dt * 8 + 2 * c4;
            size_t t0 = (size_t)(bw * NTOK + row0) * DIMC + col;
            size_t t1 = (size_t)(bw * NTOK + row1) * DIMC + col;
            *(__nv_bfloat162*)(g_attnout + t0) =
                __nv_bfloat162(__float2bfloat16(oacc[dt][0] * inv0), __float2bfloat16(oacc[dt][1] * inv0));
            *(__nv_bfloat162*)(g_attnout + t1) =
                __nv_bfloat162(__float2bfloat16(oacc[dt][2] * inv1), __float2bfloat16(oacc[dt][3] * inv1));
        }
        __syncthreads();
    }
}

// ---------------- un-window + residual + LN2 (warp per token) ----------------
__global__ __launch_bounds__(256) void unwin_res_ln2_kernel(const float* __restrict__ x,
                                                             const float* __restrict__ w,
                                                             const float* __restrict__ b) {
    int t = blockIdx.x * 8 + (threadIdx.x >> 5);
    int lane = threadIdx.x & 31;
    int pl = t / (91 * 180);
    int rem = t - pl * (91 * 180);
    int lat = rem / 180, lon = rem % 180;
    int pl_p  = (pl + 7) & 7;
    int lat_p = (lat + 95) % 96;
    int lon_p = (lon + 174) % 180;
    int plg = pl_p >> 1, wp_i = pl_p & 1;
    int latg = lat_p / 6, wa_i = lat_p % 6;
    int li = lon_p / 12, wo_i = lon_p % 12;
    int wdw = plg * 16 + latg;
    int n = (wp_i * 6 + wa_i) * 12 + wo_i;
    size_t slot = ((size_t)((li * NWIN + wdw) * NTOK + n)) * DIMC;
    size_t base = (size_t)t * DIMC;
    float v[6]; float s = 0.f, s2 = 0.f;
    #pragma unroll
    for (int k = 0; k < 6; k++) {
        int c = lane + 32 * k;
        float vv = x[base + c] + __bfloat162float(g_projout[slot + c]);
        v[k] = vv; s += vv; s2 += vv * vv;
        g_x1[base + c] = vv;
    }
    #pragma unroll
    for (int o = 16; o > 0; o >>= 1) {
        s  += __shfl_xor_sync(0xffffffffu, s, o);
        s2 += __shfl_xor_sync(0xffffffffu, s2, o);
    }
    float mean = s * (1.f / 192.f);
    float var  = s2 * (1.f / 192.f) - mean * mean;
    float rstd = rsqrtf(var + 1e-5f);
    #pragma unroll
    for (int k = 0; k < 6; k++) {
        int c = lane + 32 * k;
        float h = (v[k] - mean) * rstd * w[c] + b[c];
        g_h2in[base + c] = __float2bfloat16(h);
    }
}

// ---------------- launch ----------------
extern "C" void kernel_launch(void* const* d_in, const int* in_sizes, int n_in,
                              void* d_out, int out_size) {
    const float* x     = (const float*)d_in[0];
    const float* n1w   = (const float*)d_in[1];
    const float* n1b   = (const float*)d_in[2];
    const float* qkvw  = (const float*)d_in[3];
    const float* qkvb  = (const float*)d_in[4];
    const float* btab  = (const float*)d_in[5];
    const float* projw = (const float*)d_in[6];
    const float* projb = (const float*)d_in[7];
    const float* n2w   = (const float*)d_in[8];
    const float* n2b   = (const float*)d_in[9];
    const float* fc1w  = (const float*)d_in[10];
    const float* fc1b  = (const float*)d_in[11];
    const float* fc2w  = (const float*)d_in[12];
    const float* fc2b  = (const float*)d_in[13];
    float* out = (float*)d_out;

    void *pA1, *pqkv, *pattn, *pproj, *px1, *ph2in, *ph2mid;
    void *pwqkv, *pwproj, *pwfc1, *pwfc2;
    cudaGetSymbolAddress(&pA1, g_A1);
    cudaGetSymbolAddress(&pqkv, g_qkv);
    cudaGetSymbolAddress(&pattn, g_attnout);
    cudaGetSymbolAddress(&pproj, g_projout);
    cudaGetSymbolAddress(&px1, g_x1);
    cudaGetSymbolAddress(&ph2in, g_h2in);
    cudaGetSymbolAddress(&ph2mid, g_h2mid);
    cudaGetSymbolAddress(&pwqkv, g_wqkv);
    cudaGetSymbolAddress(&pwproj, g_wproj);
    cudaGetSymbolAddress(&pwfc1, g_wfc1);
    cudaGetSymbolAddress(&pwfc2, g_wfc2);

    cudaFuncSetAttribute(gemm2<1>, cudaFuncAttributeMaxDynamicSharedMemorySize, GEMM_SMEM);
    cudaFuncSetAttribute(gemm2<2>, cudaFuncAttributeMaxDynamicSharedMemorySize, GEMM_SMEM);
    cudaFuncSetAttribute(gemm2<3>, cudaFuncAttributeMaxDynamicSharedMemorySize, GEMM_SMEM);
    cudaFuncSetAttribute(attn_kernel, cudaFuncAttributeMaxDynamicSharedMemorySize, ATTN_SMEM);

    // 1: merged weight conversions
    wconv_kernel<<<1728, 256>>>(qkvw, projw, fc1w, fc2w);

    // 2: bias table transpose
    btab_t_kernel<<<(BROWS * NWIN * NHEAD + 255) / 256, 256>>>(btab);

    // 3: LN1 + window partition
    ln1_window_kernel<<<TOKW / 8, 256>>>(x, n1w, n1b);

    // 4: QKV GEMM -> bf16
    gemm2<1><<<dim3(3, TOKW / BM), 512, GEMM_SMEM>>>(TOKW, 3 * DIMC, DIMC,
        (const __nv_bfloat16*)pA1, (const __nv_bfloat16*)pwqkv, qkvb,
        (__nv_bfloat16*)pqkv, nullptr, nullptr);

    // 5: fused windowed attention
    attn_kernel<<<dim3(NHEAD, NWIN), 288, ATTN_SMEM>>>();

    // 6: proj GEMM -> bf16 (window layout)
    gemm2<1><<<dim3(1, TOKW / BM), 512, GEMM_SMEM>>>(TOKW, DIMC, DIMC,
        (const __nv_bfloat16*)pattn, (const __nv_bfloat16*)pwproj, projb,
        (__nv_bfloat16*)pproj, nullptr, nullptr);

    // 7: un-window + residual + LN2
    unwin_res_ln2_kernel<<<L_TOK / 8, 256>>>(x, n2w, n2b);

    // 8: fc1 (+ exact GELU) -> bf16
    gemm2<2><<<dim3(4, (L_TOK + BM - 1) / BM), 512, GEMM_SMEM>>>(L_TOK, HID, DIMC,
        (const __nv_bfloat16*)ph2in, (const __nv_bfloat16*)pwfc1, fc1b,
        (__nv_bfloat16*)ph2mid, nullptr, nullptr);

    // 9: fc2 + residual -> d_out
    gemm2<3><<<dim3(1, (L_TOK + BM - 1) / BM), 512, GEMM_SMEM>>>(L_TOK, DIMC, HID,
        (const __nv_bfloat16*)ph2mid, (const __nv_bfloat16*)pwfc2, fc2b,
        nullptr, (const float*)px1, out);
}

// round 13
// speedup vs baseline: 1.1239x; 1.1239x over previous
#include <cuda_runtime.h>
#include <cuda_bf16.h>
#include <math.h>
#include <stdint.h>

// ---------------- problem constants ----------------
#define L_TOK   131040          // 8*91*180
#define TOKW    138240          // 960 windows * 144 tokens
#define DIMC    192
#define HID     768
#define NHEAD   6
#define HDIM    32
#define NTOK    144             // tokens per window (2*6*12)
#define NWIN    64              // windows per lon-group (4*16)
#define NLON    15
#define BWN     960             // NLON*NWIN
#define BROWS   3312            // bias table rows: 4*36*23

// GEMM tiling (round-8 proven: SW128 swizzle, BM=64, BK=64, 2 CTAs/SM)
#define BM 64
#define BN 192
#define BK 64
#define GSTAGES 3
#define ASTG (BM * 128)                  // 8192 B
#define BSTG (BN * 128)                  // 24576 B
#define STGB (ASTG + BSTG)               // 32768 B
#define GEMM_SMEM (STGB * GSTAGES)       // 98304 B

// attention smem layout
#define APAD 40                          // row stride in halves for q/k/v
#define MATH (NTOK * APAD)               // 5760 halves per matrix
#define MATB (MATH * 2)                  // 11520 bytes
#define STAGEB (3 * MATB)                // 34560 bytes per stage
#define PADB 146                         // bias row stride (halves)
#define BIASB (NTOK * PADB * 2)          // 42048 bytes (multiple of 16)
#define ATTN_SMEM (2 * STAGEB + BIASB + 2 * NTOK * 4)   // 112320
#define LI_PER_BLK 5                     // lon-groups per attention block (z-split)

// ---------------- scratch buffers ----------------
__device__ __nv_bfloat16 g_A1[(size_t)TOKW * DIMC];
__device__ __nv_bfloat16 g_qkv[(size_t)TOKW * 3 * DIMC];
__device__ float         g_btabT[(size_t)NWIN * NHEAD * BROWS];            // [b2][bidx]
__device__ __nv_bfloat16 g_biasPre[(size_t)NHEAD * NWIN * NTOK * PADB];    // padded bf16
__device__ __nv_bfloat16 g_attnout[(size_t)TOKW * DIMC];
__device__ __nv_bfloat16 g_projout[(size_t)TOKW * DIMC];
__device__ float         g_x1[(size_t)L_TOK * DIMC];
__device__ __nv_bfloat16 g_h2in[(size_t)L_TOK * DIMC];
__device__ __nv_bfloat16 g_h2mid[(size_t)L_TOK * HID];
__device__ __nv_bfloat16 g_wqkv[3 * DIMC * DIMC];
__device__ __nv_bfloat16 g_wproj[DIMC * DIMC];
__device__ __nv_bfloat16 g_wfc1[HID * DIMC];
__device__ __nv_bfloat16 g_wfc2[DIMC * HID];

// ---------------- helpers ----------------
__device__ __forceinline__ void cp_async16(uint32_t saddr, const void* gptr, bool pred) {
    int sz = pred ? 16 : 0;
    asm volatile("cp.async.cg.shared.global [%0], [%1], 16, %2;\n"
                 :: "r"(saddr), "l"(gptr), "r"(sz));
}

__device__ __forceinline__ void ldsm4(uint32_t* r, uint32_t addr) {
    asm volatile("ldmatrix.sync.aligned.m8n8.x4.shared.b16 {%0,%1,%2,%3}, [%4];\n"
                 : "=r"(r[0]), "=r"(r[1]), "=r"(r[2]), "=r"(r[3]) : "r"(addr));
}

__device__ __forceinline__ void ldsm4t(uint32_t* r, uint32_t addr) {
    asm volatile("ldmatrix.sync.aligned.m8n8.x4.trans.shared.b16 {%0,%1,%2,%3}, [%4];\n"
                 : "=r"(r[0]), "=r"(r[1]), "=r"(r[2]), "=r"(r[3]) : "r"(addr));
}

__device__ __forceinline__ void mma16816(float* d, const uint32_t* a, const uint32_t* b) {
    asm volatile(
        "mma.sync.aligned.m16n8k16.row.col.f32.bf16.bf16.f32 "
        "{%0,%1,%2,%3}, {%4,%5,%6,%7}, {%8,%9}, {%0,%1,%2,%3};\n"
        : "+f"(d[0]), "+f"(d[1]), "+f"(d[2]), "+f"(d[3])
        : "r"(a[0]), "r"(a[1]), "r"(a[2]), "r"(a[3]), "r"(b[0]), "r"(b[1]));
}

__device__ __forceinline__ uint32_t packbf2(float lo, float hi) {
    __nv_bfloat162 p = __nv_bfloat162(__float2bfloat16(lo), __float2bfloat16(hi));
    return *reinterpret_cast<uint32_t*>(&p);
}

// ---------------- merged weight conversion ----------------
__global__ __launch_bounds__(256) void wconv_kernel(
    const float* __restrict__ s0, const float* __restrict__ s1,
    const float* __restrict__ s2, const float* __restrict__ s3) {
    int i = blockIdx.x * 256 + threadIdx.x;
    if (i < 110592)      g_wqkv[i]  = __float2bfloat16(s0[i]);
    else if (i < 147456) { int j = i - 110592;  g_wproj[j] = __float2bfloat16(s1[j]); }
    else if (i < 294912) { int j = i - 147456;  g_wfc1[j]  = __float2bfloat16(s2[j]); }
    else if (i < 442368) { int j = i - 294912;  g_wfc2[j]  = __float2bfloat16(s3[j]); }
}

// ---------------- bias table transpose: [bidx][b2] -> [b2][bidx] ----------------
__global__ __launch_bounds__(256) void btab_t_kernel(const float* __restrict__ btab) {
    int e = blockIdx.x * 256 + threadIdx.x;
    if (e < BROWS * NWIN * NHEAD) {
        int b2 = e / BROWS, bidx = e - b2 * BROWS;
        g_btabT[e] = btab[(size_t)bidx * (NWIN * NHEAD) + b2];
    }
}

// ---------------- bias precompute: [head][wdw][i][PADB] bf16, coalesced writes ----------
__global__ __launch_bounds__(256) void bias_pre_kernel() {
    int hw = blockIdx.x;                       // head*NWIN + wdw
    int head = hw / NWIN, wdw = hw - head * NWIN;
    const float* bt = g_btabT + (size_t)(wdw * NHEAD + head) * BROWS;
    __nv_bfloat16* dst = g_biasPre + (size_t)hw * NTOK * PADB;
    for (int e = threadIdx.x; e < NTOK * NTOK; e += 256) {
        int i = e / NTOK, j = e - i * NTOK;
        int zi = i / 72, hi = (i / 12) % 6, wi = i % 12;
        int zj = j / 72, hj = (j / 12) % 6, wj = j % 12;
        int bidx = (zi + 2 * zj) * 828 + (hi + 6 * hj) * 23 + (wi - wj + 11);
        dst[i * PADB + j] = __float2bfloat16(bt[bidx]);
    }
}

// ---------------- LN1 + pad + roll + window partition (warp per token) ----------------
__global__ __launch_bounds__(256) void ln1_window_kernel(const float* __restrict__ x,
                                                          const float* __restrict__ w,
                                                          const float* __restrict__ b) {
    int t = blockIdx.x * 8 + (threadIdx.x >> 5);
    int lane = threadIdx.x & 31;
    int bw = t / NTOK, n = t - bw * NTOK;
    int li = bw >> 6, wdw = bw & 63;
    int wp_i = n / 72, wa_i = (n / 12) % 6, wo_i = n % 12;
    int pl_p  = (wdw >> 4) * 2 + wp_i;
    int lat_p = (wdw & 15) * 6 + wa_i;
    int lon_p = li * 12 + wo_i;
    int pl_s  = (pl_p + 1) & 7;
    int lat_s = (lat_p + 3) % 96;
    int lon_s = (lon_p + 6) % 180;
    int lat_o = lat_s - 2;
    bool valid = (lat_o >= 0) && (lat_o < 91);
    size_t src = valid ? ((size_t)(pl_s * 91 + lat_o) * 180 + lon_s) * DIMC : 0;
    float v[6]; float s = 0.f, s2 = 0.f;
    #pragma unroll
    for (int k = 0; k < 6; k++) {
        float vv = valid ? x[src + lane + 32 * k] : 0.f;
        v[k] = vv; s += vv; s2 += vv * vv;
    }
    #pragma unroll
    for (int o = 16; o > 0; o >>= 1) {
        s  += __shfl_xor_sync(0xffffffffu, s, o);
        s2 += __shfl_xor_sync(0xffffffffu, s2, o);
    }
    float mean = s * (1.f / 192.f);
    float var  = s2 * (1.f / 192.f) - mean * mean;
    float rstd = rsqrtf(var + 1e-5f);
    #pragma unroll
    for (int k = 0; k < 6; k++) {
        int c = lane + 32 * k;
        float h = valid ? (v[k] - mean) * rstd * w[c] + b[c] : 0.f;
        g_A1[(size_t)t * DIMC + c] = __float2bfloat16(h);
    }
}

// ---------------- bf16 GEMM: BM=64, BK=64, SW128 swizzle, 2 CTAs/SM, warp tile 32x48 ----
// MODE 1: bf16 out + bias   MODE 2: gelu(acc+bias) -> bf16   MODE 3: Out = X1 + acc + bias (fp32)
template <int MODE>
__global__ __launch_bounds__(256, 2) void gemm2(
    int M, int N, int K,
    const __nv_bfloat16* __restrict__ A,
    const __nv_bfloat16* __restrict__ Bw,
    const float* __restrict__ bias,
    __nv_bfloat16* __restrict__ Cb,
    const float* __restrict__ X1,
    float* __restrict__ Out) {
    extern __shared__ __align__(16) unsigned char smraw[];
    uint32_t smem_u32 = (uint32_t)__cvta_generic_to_shared(smraw);

    const int tid = threadIdx.x;
    const int lane = tid & 31, warp = tid >> 5;
    const int m0 = blockIdx.y * BM;
    const int n0 = blockIdx.x * BN;
    const int wm = (warp >> 2) * 32;   // 2 warp rows * 32
    const int wn = (warp & 3) * 48;    // 4 warp cols * 48
    const int KT = K >> 6;             // k-chunks of 64

    float acc[2][6][4];
    #pragma unroll
    for (int a = 0; a < 2; a++)
        #pragma unroll
        for (int b2 = 0; b2 < 6; b2++)
            #pragma unroll
            for (int c = 0; c < 4; c++) acc[a][b2][c] = 0.f;

    auto load_stage = [&](int stage, int kt) {
        const int kb = kt << 6;
        uint32_t abase = smem_u32 + stage * STGB;
        #pragma unroll
        for (int it = 0; it < 2; it++) {   // A: 64 rows * 8 chunks = 512
            int q = tid + it * 256;
            int row = q >> 3, c = q & 7;
            int gr = m0 + row;
            bool p = gr < M;
            const __nv_bfloat16* gp = A + (size_t)(p ? gr : 0) * K + kb + c * 8;
            cp_async16(abase + (uint32_t)(row * 128 + ((c ^ (row & 7)) << 4)), gp, p);
        }
        uint32_t bbase = abase + ASTG;
        #pragma unroll
        for (int it = 0; it < 6; it++) {   // B: 192 rows * 8 chunks = 1536
            int q = tid + it * 256;
            int row = q >> 3, c = q & 7;
            const __nv_bfloat16* gp = Bw + (size_t)(n0 + row) * K + kb + c * 8;
            cp_async16(bbase + (uint32_t)(row * 128 + ((c ^ (row & 7)) << 4)), gp, true);
        }
    };

    #pragma unroll
    for (int s = 0; s < GSTAGES - 1; s++) {
        load_stage(s, s);
        asm volatile("cp.async.commit_group;\n");
    }

    for (int kt = 0; kt < KT; kt++) {
        asm volatile("cp.async.wait_group 1;\n");
        __syncthreads();
        int kn = kt + GSTAGES - 1;
        if (kn < KT) load_stage(kn % GSTAGES, kn);
        asm volatile("cp.async.commit_group;\n");

        uint32_t abase = smem_u32 + (kt % GSTAGES) * STGB;
        uint32_t bbase = abase + ASTG;
        #pragma unroll
        for (int t = 0; t < 4; t++) {      // 4 k16 steps inside the 64-chunk
            uint32_t af[2][4], bfr[3][4];
            #pragma unroll
            for (int mi = 0; mi < 2; mi++) {
                int r = wm + mi * 16 + (lane & 15);
                int c = 2 * t + ((lane & 16) >> 4);
                ldsm4(af[mi], abase + (uint32_t)(r * 128 + ((c ^ (r & 7)) << 4)));
            }
            #pragma unroll
            for (int nb = 0; nb < 3; nb++) {
                int r = wn + nb * 16 + (lane & 7) + ((lane & 16) >> 1);
                int c = 2 * t + ((lane & 8) >> 3);
                ldsm4(bfr[nb], bbase + (uint32_t)(r * 128 + ((c ^ (r & 7)) << 4)));
            }
            #pragma unroll
            for (int mi = 0; mi < 2; mi++)
                #pragma unroll
                for (int ni = 0; ni < 6; ni++)
                    mma16816(acc[mi][ni], af[mi], &bfr[ni >> 1][(ni & 1) * 2]);
        }
    }

    // epilogue
    const int g = lane >> 2, c4 = lane & 3;
    #pragma unroll
    for (int mi = 0; mi < 2; mi++) {
        #pragma unroll
        for (int ni = 0; ni < 6; ni++) {
            int row0 = m0 + wm + mi * 16 + g;
            int col0 = n0 + wn + ni * 8 + 2 * c4;
            float2 bv = *(const float2*)(bias + col0);
            #pragma unroll
            for (int rr = 0; rr < 2; rr++) {
                int row = row0 + rr * 8;
                if (row >= M) continue;
                float v0 = acc[mi][ni][rr * 2 + 0] + bv.x;
                float v1 = acc[mi][ni][rr * 2 + 1] + bv.y;
                size_t off = (size_t)row * N + col0;
                if (MODE == 1) {
                    *(__nv_bfloat162*)(Cb + off) =
                        __nv_bfloat162(__float2bfloat16(v0), __float2bfloat16(v1));
                } else if (MODE == 2) {
                    float g0 = 0.5f * v0 * (1.0f + erff(v0 * 0.70710678118654752f));
                    float g1 = 0.5f * v1 * (1.0f + erff(v1 * 0.70710678118654752f));
                    *(__nv_bfloat162*)(Cb + off) =
                        __nv_bfloat162(__float2bfloat16(g0), __float2bfloat16(g1));
                } else {
                    float2 xv = *(const float2*)(X1 + off);
                    *(float2*)(Out + off) = make_float2(xv.x + v0, xv.y + v1);
                }
            }
        }
    }
}

// ---------------- tensor-core windowed attention, z-split, streamed bias ----------
// block = (head, wdw, z); li in [z*5, z*5+5); bias slice streamed via cp.async.
__global__ __launch_bounds__(288, 1) void attn_kernel() {
    const int head = blockIdx.x;
    const int wdw = blockIdx.y;
    const int li0 = blockIdx.z * LI_PER_BLK;
    const int tid = threadIdx.x;
    const int lane = tid & 31;
    const int warp = tid >> 5;

    extern __shared__ __align__(16) unsigned char smraw[];
    __nv_bfloat16* sbias = (__nv_bfloat16*)(smraw + 2 * STAGEB);
    int* sid0  = (int*)(smraw + 2 * STAGEB + BIASB);
    int* sid14 = sid0 + NTOK;
    uint32_t squ = (uint32_t)__cvta_generic_to_shared(smraw);
    const uint32_t sbias_u = squ + 2 * STAGEB;

    auto load_st = [&](int st, int li) {
        int bw = li * NWIN + wdw;
        const __nv_bfloat16* gb = g_qkv + (size_t)bw * NTOK * (3 * DIMC) + head * HDIM;
        uint32_t sb = squ + st * STAGEB;
        #pragma unroll
        for (int s = 0; s < 6; s++) {
            int c = tid + s * 288;
            int mat = c / 576, rem = c - mat * 576, j = rem >> 2, q16 = rem & 3;
            const void* gp = gb + (size_t)j * (3 * DIMC) + mat * DIMC + q16 * 8;
            cp_async16(sb + (uint32_t)(mat * MATB + j * (APAD * 2) + q16 * 16), gp, true);
        }
    };

    // G0: first qkv tile
    load_st(li0 & 1, li0);
    asm volatile("cp.async.commit_group;\n");

    // G1: bias slice (flat 16B stream, 2628 chunks)
    {
        const unsigned char* gbias =
            (const unsigned char*)(g_biasPre + (size_t)(head * NWIN + wdw) * NTOK * PADB);
        for (int c = tid; c < BIASB / 16; c += 288)
            cp_async16(sbias_u + (uint32_t)(c * 16), gbias + c * 16, true);
        asm volatile("cp.async.commit_group;\n");
    }

    if (tid < NTOK) {
        int n = tid;
        int wp_i = n / 72, wa_i = (n / 12) % 6, wo_i = n % 12;
        int pl_p  = (wdw >> 4) * 2 + wp_i;
        int lat_p = (wdw & 15) * 6 + wa_i;
        int rpl  = pl_p  < 6  ? 0 : (pl_p  < 7  ? 1 : 2);
        int rlat = lat_p < 90 ? 0 : (lat_p < 93 ? 1 : 2);
        int base = (rpl * 3 + rlat) * 3;
        sid0[n]  = base;
        sid14[n] = base + ((168 + wo_i) >= 174 ? 1 : 0);
    }

    const int qrow0 = warp * 16;
    const int g = lane >> 2, c4 = lane & 3;
    const int row0 = qrow0 + g, row1 = row0 + 8;
    const float qscale = 0.17677669529663687f;

    for (int li = li0; li < li0 + LI_PER_BLK; li++) {
        if (li + 1 < li0 + LI_PER_BLK) {
            load_st((li + 1) & 1, li + 1);
            asm volatile("cp.async.commit_group;\n");
            asm volatile("cp.async.wait_group 1;\n");
        } else {
            asm volatile("cp.async.wait_group 0;\n");
        }
        __syncthreads();

        uint32_t sq_b = squ + (li & 1) * STAGEB;
        uint32_t sk_b = sq_b + MATB;
        uint32_t sv_b = sk_b + MATB;
        const int* sregp = (li == 14) ? sid14 : sid0;

        uint32_t aq[2][4];
        #pragma unroll
        for (int kkidx = 0; kkidx < 2; kkidx++) {
            uint32_t addr = sq_b + (uint32_t)((qrow0 + (lane & 15)) * (APAD * 2)
                                              + kkidx * 32 + (lane & 16));
            ldsm4(aq[kkidx], addr);
        }

        float sacc[18][4];
        #pragma unroll
        for (int t = 0; t < 18; t++)
            #pragma unroll
            for (int c = 0; c < 4; c++) sacc[t][c] = 0.f;

        #pragma unroll
        for (int nt = 0; nt < 9; nt++) {
            #pragma unroll
            for (int kkidx = 0; kkidx < 2; kkidx++) {
                uint32_t bk[4];
                uint32_t addr = sk_b +
                    (uint32_t)((nt * 16 + (lane & 7) + ((lane & 16) >> 1)) * (APAD * 2)
                               + kkidx * 32 + (lane & 8) * 2);
                ldsm4(bk, addr);
                mma16816(sacc[2 * nt],     aq[kkidx], &bk[0]);
                mma16816(sacc[2 * nt + 1], aq[kkidx], &bk[2]);
            }
        }

        const int rg0 = sregp[row0], rg1 = sregp[row1];
        #pragma unroll
        for (int t = 0; t < 18; t++) {
            int col = t * 8 + 2 * c4;
            float2 b0 = __bfloat1622float2(*(const __nv_bfloat162*)(sbias + row0 * PADB + col));
            float2 b1 = __bfloat1622float2(*(const __nv_bfloat162*)(sbias + row1 * PADB + col));
            int rc0 = sregp[col], rc1 = sregp[col + 1];
            sacc[t][0] = fmaf(sacc[t][0], qscale, b0.x + (rc0 != rg0 ? -100.f : 0.f));
            sacc[t][1] = fmaf(sacc[t][1], qscale, b0.y + (rc1 != rg0 ? -100.f : 0.f));
            sacc[t][2] = fmaf(sacc[t][2], qscale, b1.x + (rc0 != rg1 ? -100.f : 0.f));
            sacc[t][3] = fmaf(sacc[t][3], qscale, b1.y + (rc1 != rg1 ? -100.f : 0.f));
        }

        float mx0 = -1e30f, mx1 = -1e30f;
        #pragma unroll
        for (int t = 0; t < 18; t++) {
            mx0 = fmaxf(mx0, fmaxf(sacc[t][0], sacc[t][1]));
            mx1 = fmaxf(mx1, fmaxf(sacc[t][2], sacc[t][3]));
        }
        #pragma unroll
        for (int o = 1; o <= 2; o <<= 1) {
            mx0 = fmaxf(mx0, __shfl_xor_sync(0xffffffffu, mx0, o));
            mx1 = fmaxf(mx1, __shfl_xor_sync(0xffffffffu, mx1, o));
        }
        float sum0 = 0.f, sum1 = 0.f;
        #pragma unroll
        for (int t = 0; t < 18; t++) {
            sacc[t][0] = __expf(sacc[t][0] - mx0);
            sacc[t][1] = __expf(sacc[t][1] - mx0);
            sacc[t][2] = __expf(sacc[t][2] - mx1);
            sacc[t][3] = __expf(sacc[t][3] - mx1);
            sum0 += sacc[t][0] + sacc[t][1];
            sum1 += sacc[t][2] + sacc[t][3];
        }
        #pragma unroll
        for (int o = 1; o <= 2; o <<= 1) {
            sum0 += __shfl_xor_sync(0xffffffffu, sum0, o);
            sum1 += __shfl_xor_sync(0xffffffffu, sum1, o);
        }
        float inv0 = 1.f / sum0, inv1 = 1.f / sum1;

        uint32_t ap[9][4];
        #pragma unroll
        for (int kt = 0; kt < 9; kt++) {
            ap[kt][0] = packbf2(sacc[2 * kt][0],     sacc[2 * kt][1]);
            ap[kt][1] = packbf2(sacc[2 * kt][2],     sacc[2 * kt][3]);
            ap[kt][2] = packbf2(sacc[2 * kt + 1][0], sacc[2 * kt + 1][1]);
            ap[kt][3] = packbf2(sacc[2 * kt + 1][2], sacc[2 * kt + 1][3]);
        }

        float oacc[4][4];
        #pragma unroll
        for (int t = 0; t < 4; t++)
            #pragma unroll
            for (int c = 0; c < 4; c++) oacc[t][c] = 0.f;

        #pragma unroll
        for (int kt = 0; kt < 9; kt++) {
            #pragma unroll
            for (int dh = 0; dh < 2; dh++) {
                uint32_t bv[4];
                uint32_t addr = sv_b +
                    (uint32_t)((kt * 16 + (lane & 15)) * (APAD * 2) + dh * 32 + (lane & 16));
                ldsm4t(bv, addr);
                mma16816(oacc[2 * dh],     ap[kt], &bv[0]);
                mma16816(oacc[2 * dh + 1], ap[kt], &bv[2]);
            }
        }

        int bw = li * NWIN + wdw;
        #pragma unroll
        for (int dt = 0; dt < 4; dt++) {
            int col = head * HDIM + dt * 8 + 2 * c4;
            size_t t0 = (size_t)(bw * NTOK + row0) * DIMC + col;
            size_t t1 = (size_t)(bw * NTOK + row1) * DIMC + col;
            *(__nv_bfloat162*)(g_attnout + t0) =
                __nv_bfloat162(__float2bfloat16(oacc[dt][0] * inv0), __float2bfloat16(oacc[dt][1] * inv0));
            *(__nv_bfloat162*)(g_attnout + t1) =
                __nv_bfloat162(__float2bfloat16(oacc[dt][2] * inv1), __float2bfloat16(oacc[dt][3] * inv1));
        }
        __syncthreads();
    }
}

// ---------------- un-window + residual + LN2 (warp per token) ----------------
__global__ __launch_bounds__(256) void unwin_res_ln2_kernel(const float* __restrict__ x,
                                                             const float* __restrict__ w,
                                                             const float* __restrict__ b) {
    int t = blockIdx.x * 8 + (threadIdx.x >> 5);
    int lane = threadIdx.x & 31;
    int pl = t / (91 * 180);
    int rem = t - pl * (91 * 180);
    int lat = rem / 180, lon = rem % 180;
    int pl_p  = (pl + 7) & 7;
    int lat_p = (lat + 95) % 96;
    int lon_p = (lon + 174) % 180;
    int plg = pl_p >> 1, wp_i = pl_p & 1;
    int latg = lat_p / 6, wa_i = lat_p % 6;
    int li = lon_p / 12, wo_i = lon_p % 12;
    int wdw = plg * 16 + latg;
    int n = (wp_i * 6 + wa_i) * 12 + wo_i;
    size_t slot = ((size_t)((li * NWIN + wdw) * NTOK + n)) * DIMC;
    size_t base = (size_t)t * DIMC;
    float v[6]; float s = 0.f, s2 = 0.f;
    #pragma unroll
    for (int k = 0; k < 6; k++) {
        int c = lane + 32 * k;
        float vv = x[base + c] + __bfloat162float(g_projout[slot + c]);
        v[k] = vv; s += vv; s2 += vv * vv;
        g_x1[base + c] = vv;
    }
    #pragma unroll
    for (int o = 16; o > 0; o >>= 1) {
        s  += __shfl_xor_sync(0xffffffffu, s, o);
        s2 += __shfl_xor_sync(0xffffffffu, s2, o);
    }
    float mean = s * (1.f / 192.f);
    float var  = s2 * (1.f / 192.f) - mean * mean;
    float rstd = rsqrtf(var + 1e-5f);
    #pragma unroll
    for (int k = 0; k < 6; k++) {
        int c = lane + 32 * k;
        float h = (v[k] - mean) * rstd * w[c] + b[c];
        g_h2in[base + c] = __float2bfloat16(h);
    }
}

// ---------------- launch ----------------
extern "C" void kernel_launch(void* const* d_in, const int* in_sizes, int n_in,
                              void* d_out, int out_size) {
    const float* x     = (const float*)d_in[0];
    const float* n1w   = (const float*)d_in[1];
    const float* n1b   = (const float*)d_in[2];
    const float* qkvw  = (const float*)d_in[3];
    const float* qkvb  = (const float*)d_in[4];
    const float* btab  = (const float*)d_in[5];
    const float* projw = (const float*)d_in[6];
    const float* projb = (const float*)d_in[7];
    const float* n2w   = (const float*)d_in[8];
    const float* n2b   = (const float*)d_in[9];
    const float* fc1w  = (const float*)d_in[10];
    const float* fc1b  = (const float*)d_in[11];
    const float* fc2w  = (const float*)d_in[12];
    const float* fc2b  = (const float*)d_in[13];
    float* out = (float*)d_out;

    void *pA1, *pqkv, *pattn, *pproj, *px1, *ph2in, *ph2mid;
    void *pwqkv, *pwproj, *pwfc1, *pwfc2;
    cudaGetSymbolAddress(&pA1, g_A1);
    cudaGetSymbolAddress(&pqkv, g_qkv);
    cudaGetSymbolAddress(&pattn, g_attnout);
    cudaGetSymbolAddress(&pproj, g_projout);
    cudaGetSymbolAddress(&px1, g_x1);
    cudaGetSymbolAddress(&ph2in, g_h2in);
    cudaGetSymbolAddress(&ph2mid, g_h2mid);
    cudaGetSymbolAddress(&pwqkv, g_wqkv);
    cudaGetSymbolAddress(&pwproj, g_wproj);
    cudaGetSymbolAddress(&pwfc1, g_wfc1);
    cudaGetSymbolAddress(&pwfc2, g_wfc2);

    cudaFuncSetAttribute(gemm2<1>, cudaFuncAttributeMaxDynamicSharedMemorySize, GEMM_SMEM);
    cudaFuncSetAttribute(gemm2<2>, cudaFuncAttributeMaxDynamicSharedMemorySize, GEMM_SMEM);
    cudaFuncSetAttribute(gemm2<3>, cudaFuncAttributeMaxDynamicSharedMemorySize, GEMM_SMEM);
    cudaFuncSetAttribute(attn_kernel, cudaFuncAttributeMaxDynamicSharedMemorySize, ATTN_SMEM);

    // 1: merged weight conversions
    wconv_kernel<<<1728, 256>>>(qkvw, projw, fc1w, fc2w);

    // 2: bias table transpose
    btab_t_kernel<<<(BROWS * NWIN * NHEAD + 255) / 256, 256>>>(btab);

    // 3: bias precompute (bf16, padded, per (head,wdw))
    bias_pre_kernel<<<NHEAD * NWIN, 256>>>();

    // 4: LN1 + window partition
    ln1_window_kernel<<<TOKW / 8, 256>>>(x, n1w, n1b);

    // 5: QKV GEMM -> bf16
    gemm2<1><<<dim3(3, TOKW / BM), 256, GEMM_SMEM>>>(TOKW, 3 * DIMC, DIMC,
        (const __nv_bfloat16*)pA1, (const __nv_bfloat16*)pwqkv, qkvb,
        (__nv_bfloat16*)pqkv, nullptr, nullptr);

    // 6: fused windowed attention (z-split, streamed bias)
    attn_kernel<<<dim3(NHEAD, NWIN, NLON / LI_PER_BLK), 288, ATTN_SMEM>>>();

    // 7: proj GEMM -> bf16 (window layout)
    gemm2<1><<<dim3(1, TOKW / BM), 256, GEMM_SMEM>>>(TOKW, DIMC, DIMC,
        (const __nv_bfloat16*)pattn, (const __nv_bfloat16*)pwproj, projb,
        (__nv_bfloat16*)pproj, nullptr, nullptr);

    // 8: un-window + residual + LN2
    unwin_res_ln2_kernel<<<L_TOK / 8, 256>>>(x, n2w, n2b);

    // 9: fc1 (+ exact GELU) -> bf16
    gemm2<2><<<dim3(4, (L_TOK + BM - 1) / BM), 256, GEMM_SMEM>>>(L_TOK, HID, DIMC,
        (const __nv_bfloat16*)ph2in, (const __nv_bfloat16*)pwfc1, fc1b,
        (__nv_bfloat16*)ph2mid, nullptr, nullptr);

    // 10: fc2 + residual -> d_out
    gemm2<3><<<dim3(1, (L_TOK + BM - 1) / BM), 256, GEMM_SMEM>>>(L_TOK, DIMC, HID,
        (const __nv_bfloat16*)ph2mid, (const __nv_bfloat16*)pwfc2, fc2b,
        nullptr, (const float*)px1, out);
}

// round 14
// speedup vs baseline: 1.1370x; 1.0117x over previous
#include <cuda_runtime.h>
#include <cuda_bf16.h>
#include <math.h>
#include <stdint.h>

// ---------------- problem constants ----------------
#define L_TOK   131040          // 8*91*180
#define TOKW    138240          // 960 windows * 144 tokens
#define DIMC    192
#define HID     768
#define NHEAD   6
#define HDIM    32
#define NTOK    144             // tokens per window (2*6*12)
#define NWIN    64              // windows per lon-group (4*16)
#define NLON    15
#define BWN     960             // NLON*NWIN
#define BROWS   3312            // bias table rows: 4*36*23

// GEMM tiling (round-8 proven: SW128 swizzle, BM=64, BK=64, 2 CTAs/SM)
#define BM 64
#define BN 192
#define BK 64
#define GSTAGES 3
#define ASTG (BM * 128)                  // 8192 B
#define BSTG (BN * 128)                  // 24576 B
#define STGB (ASTG + BSTG)               // 32768 B
#define GEMM_SMEM (STGB * GSTAGES)       // 98304 B

// attention smem layout
#define APAD 40                          // row stride in halves for q/k/v
#define MATH (NTOK * APAD)               // 5760 halves per matrix
#define MATB (MATH * 2)                  // 11520 bytes
#define STAGEB (3 * MATB)                // 34560 bytes per stage
#define PADB 146                         // bias row stride (halves)
#define BIASB (NTOK * PADB * 2)          // 42048 bytes (multiple of 16)
#define ATTN_SMEM (2 * STAGEB + BIASB + 2 * NTOK * 4)   // 112320
#define LI_PER_BLK 5                     // lon-groups per attention block (z-split)

// ---------------- scratch buffers ----------------
__device__ __nv_bfloat16 g_A1[(size_t)TOKW * DIMC];
__device__ __nv_bfloat16 g_qkv[(size_t)TOKW * 3 * DIMC];
__device__ float         g_btabT[(size_t)NWIN * NHEAD * BROWS];            // [b2][bidx]
__device__ __nv_bfloat16 g_biasPre[(size_t)NHEAD * NWIN * NTOK * PADB];    // padded bf16
__device__ __nv_bfloat16 g_attnout[(size_t)TOKW * DIMC];
__device__ float         g_x1[(size_t)L_TOK * DIMC];
__device__ __nv_bfloat16 g_h2in[(size_t)L_TOK * DIMC];
__device__ __nv_bfloat16 g_h2mid[(size_t)L_TOK * HID];
__device__ __nv_bfloat16 g_wqkv[3 * DIMC * DIMC];
__device__ __nv_bfloat16 g_wproj[DIMC * DIMC];
__device__ __nv_bfloat16 g_wfc1[HID * DIMC];
__device__ __nv_bfloat16 g_wfc2[DIMC * HID];

// ---------------- helpers ----------------
__device__ __forceinline__ void cp_async16(uint32_t saddr, const void* gptr, bool pred) {
    int sz = pred ? 16 : 0;
    asm volatile("cp.async.cg.shared.global [%0], [%1], 16, %2;\n"
                 :: "r"(saddr), "l"(gptr), "r"(sz));
}

__device__ __forceinline__ void ldsm4(uint32_t* r, uint32_t addr) {
    asm volatile("ldmatrix.sync.aligned.m8n8.x4.shared.b16 {%0,%1,%2,%3}, [%4];\n"
                 : "=r"(r[0]), "=r"(r[1]), "=r"(r[2]), "=r"(r[3]) : "r"(addr));
}

__device__ __forceinline__ void ldsm4t(uint32_t* r, uint32_t addr) {
    asm volatile("ldmatrix.sync.aligned.m8n8.x4.trans.shared.b16 {%0,%1,%2,%3}, [%4];\n"
                 : "=r"(r[0]), "=r"(r[1]), "=r"(r[2]), "=r"(r[3]) : "r"(addr));
}

__device__ __forceinline__ void mma16816(float* d, const uint32_t* a, const uint32_t* b) {
    asm volatile(
        "mma.sync.aligned.m16n8k16.row.col.f32.bf16.bf16.f32 "
        "{%0,%1,%2,%3}, {%4,%5,%6,%7}, {%8,%9}, {%0,%1,%2,%3};\n"
        : "+f"(d[0]), "+f"(d[1]), "+f"(d[2]), "+f"(d[3])
        : "r"(a[0]), "r"(a[1]), "r"(a[2]), "r"(a[3]), "r"(b[0]), "r"(b[1]));
}

__device__ __forceinline__ uint32_t packbf2(float lo, float hi) {
    __nv_bfloat162 p = __nv_bfloat162(__float2bfloat16(lo), __float2bfloat16(hi));
    return *reinterpret_cast<uint32_t*>(&p);
}

// ---------------- merged weight conversion ----------------
__global__ __launch_bounds__(256) void wconv_kernel(
    const float* __restrict__ s0, const float* __restrict__ s1,
    const float* __restrict__ s2, const float* __restrict__ s3) {
    int i = blockIdx.x * 256 + threadIdx.x;
    if (i < 110592)      g_wqkv[i]  = __float2bfloat16(s0[i]);
    else if (i < 147456) { int j = i - 110592;  g_wproj[j] = __float2bfloat16(s1[j]); }
    else if (i < 294912) { int j = i - 147456;  g_wfc1[j]  = __float2bfloat16(s2[j]); }
    else if (i < 442368) { int j = i - 294912;  g_wfc2[j]  = __float2bfloat16(s3[j]); }
}

// ---------------- bias table transpose: [bidx][b2] -> [b2][bidx] ----------------
__global__ __launch_bounds__(256) void btab_t_kernel(const float* __restrict__ btab) {
    int e = blockIdx.x * 256 + threadIdx.x;
    if (e < BROWS * NWIN * NHEAD) {
        int b2 = e / BROWS, bidx = e - b2 * BROWS;
        g_btabT[e] = btab[(size_t)bidx * (NWIN * NHEAD) + b2];
    }
}

// ---------------- bias precompute: [head][wdw][i][PADB] bf16, coalesced writes ----------
__global__ __launch_bounds__(256) void bias_pre_kernel() {
    int hw = blockIdx.x;
    int head = hw / NWIN, wdw = hw - head * NWIN;
    const float* bt = g_btabT + (size_t)(wdw * NHEAD + head) * BROWS;
    __nv_bfloat16* dst = g_biasPre + (size_t)hw * NTOK * PADB;
    for (int e = threadIdx.x; e < NTOK * NTOK; e += 256) {
        int i = e / NTOK, j = e - i * NTOK;
        int zi = i / 72, hi = (i / 12) % 6, wi = i % 12;
        int zj = j / 72, hj = (j / 12) % 6, wj = j % 12;
        int bidx = (zi + 2 * zj) * 828 + (hi + 6 * hj) * 23 + (wi - wj + 11);
        dst[i * PADB + j] = __float2bfloat16(bt[bidx]);
    }
}

// ---------------- LN1 + pad + roll + window partition (warp per token) ----------------
__global__ __launch_bounds__(256) void ln1_window_kernel(const float* __restrict__ x,
                                                          const float* __restrict__ w,
                                                          const float* __restrict__ b) {
    int t = blockIdx.x * 8 + (threadIdx.x >> 5);
    int lane = threadIdx.x & 31;
    int bw = t / NTOK, n = t - bw * NTOK;
    int li = bw >> 6, wdw = bw & 63;
    int wp_i = n / 72, wa_i = (n / 12) % 6, wo_i = n % 12;
    int pl_p  = (wdw >> 4) * 2 + wp_i;
    int lat_p = (wdw & 15) * 6 + wa_i;
    int lon_p = li * 12 + wo_i;
    int pl_s  = (pl_p + 1) & 7;
    int lat_s = (lat_p + 3) % 96;
    int lon_s = (lon_p + 6) % 180;
    int lat_o = lat_s - 2;
    bool valid = (lat_o >= 0) && (lat_o < 91);
    size_t src = valid ? ((size_t)(pl_s * 91 + lat_o) * 180 + lon_s) * DIMC : 0;
    float v[6]; float s = 0.f, s2 = 0.f;
    #pragma unroll
    for (int k = 0; k < 6; k++) {
        float vv = valid ? x[src + lane + 32 * k] : 0.f;
        v[k] = vv; s += vv; s2 += vv * vv;
    }
    #pragma unroll
    for (int o = 16; o > 0; o >>= 1) {
        s  += __shfl_xor_sync(0xffffffffu, s, o);
        s2 += __shfl_xor_sync(0xffffffffu, s2, o);
    }
    float mean = s * (1.f / 192.f);
    float var  = s2 * (1.f / 192.f) - mean * mean;
    float rstd = rsqrtf(var + 1e-5f);
    #pragma unroll
    for (int k = 0; k < 6; k++) {
        int c = lane + 32 * k;
        float h = valid ? (v[k] - mean) * rstd * w[c] + b[c] : 0.f;
        g_A1[(size_t)t * DIMC + c] = __float2bfloat16(h);
    }
}

// ---------------- bf16 GEMM: BM=64, BK=64, SW128 swizzle, 2 CTAs/SM, warp tile 32x48 ----
// MODE 1: bf16 out + bias
// MODE 2: gelu(acc+bias) -> bf16
// MODE 3: Out = X1 + acc + bias (fp32)
// MODE 4: proj epilogue: unwindow + residual(x) + LN2 -> g_x1 (fp32) + g_h2in (bf16)
template <int MODE>
__global__ __launch_bounds__(256, 2) void gemm2(
    int M, int N, int K,
    const __nv_bfloat16* __restrict__ A,
    const __nv_bfloat16* __restrict__ Bw,
    const float* __restrict__ bias,
    __nv_bfloat16* __restrict__ Cb,
    const float* __restrict__ X1,
    float* __restrict__ Out,
    const float* __restrict__ n2w,
    const float* __restrict__ n2b) {
    extern __shared__ __align__(16) unsigned char smraw[];
    uint32_t smem_u32 = (uint32_t)__cvta_generic_to_shared(smraw);

    const int tid = threadIdx.x;
    const int lane = tid & 31, warp = tid >> 5;
    const int m0 = blockIdx.y * BM;
    const int n0 = blockIdx.x * BN;
    const int wm = (warp >> 2) * 32;   // 2 warp rows * 32
    const int wn = (warp & 3) * 48;    // 4 warp cols * 48
    const int KT = K >> 6;             // k-chunks of 64

    float acc[2][6][4];
    #pragma unroll
    for (int a = 0; a < 2; a++)
        #pragma unroll
        for (int b2 = 0; b2 < 6; b2++)
            #pragma unroll
            for (int c = 0; c < 4; c++) acc[a][b2][c] = 0.f;

    auto load_stage = [&](int stage, int kt) {
        const int kb = kt << 6;
        uint32_t abase = smem_u32 + stage * STGB;
        #pragma unroll
        for (int it = 0; it < 2; it++) {   // A: 64 rows * 8 chunks = 512
            int q = tid + it * 256;
            int row = q >> 3, c = q & 7;
            int gr = m0 + row;
            bool p = gr < M;
            const __nv_bfloat16* gp = A + (size_t)(p ? gr : 0) * K + kb + c * 8;
            cp_async16(abase + (uint32_t)(row * 128 + ((c ^ (row & 7)) << 4)), gp, p);
        }
        uint32_t bbase = abase + ASTG;
        #pragma unroll
        for (int it = 0; it < 6; it++) {   // B: 192 rows * 8 chunks = 1536
            int q = tid + it * 256;
            int row = q >> 3, c = q & 7;
            const __nv_bfloat16* gp = Bw + (size_t)(n0 + row) * K + kb + c * 8;
            cp_async16(bbase + (uint32_t)(row * 128 + ((c ^ (row & 7)) << 4)), gp, true);
        }
    };

    #pragma unroll
    for (int s = 0; s < GSTAGES - 1; s++) {
        load_stage(s, s);
        asm volatile("cp.async.commit_group;\n");
    }

    for (int kt = 0; kt < KT; kt++) {
        asm volatile("cp.async.wait_group 1;\n");
        __syncthreads();
        int kn = kt + GSTAGES - 1;
        if (kn < KT) load_stage(kn % GSTAGES, kn);
        asm volatile("cp.async.commit_group;\n");

        uint32_t abase = smem_u32 + (kt % GSTAGES) * STGB;
        uint32_t bbase = abase + ASTG;
        #pragma unroll
        for (int t = 0; t < 4; t++) {
            uint32_t af[2][4], bfr[3][4];
            #pragma unroll
            for (int mi = 0; mi < 2; mi++) {
                int r = wm + mi * 16 + (lane & 15);
                int c = 2 * t + ((lane & 16) >> 4);
                ldsm4(af[mi], abase + (uint32_t)(r * 128 + ((c ^ (r & 7)) << 4)));
            }
            #pragma unroll
            for (int nb = 0; nb < 3; nb++) {
                int r = wn + nb * 16 + (lane & 7) + ((lane & 16) >> 1);
                int c = 2 * t + ((lane & 8) >> 3);
                ldsm4(bfr[nb], bbase + (uint32_t)(r * 128 + ((c ^ (r & 7)) << 4)));
            }
            #pragma unroll
            for (int mi = 0; mi < 2; mi++)
                #pragma unroll
                for (int ni = 0; ni < 6; ni++)
                    mma16816(acc[mi][ni], af[mi], &bfr[ni >> 1][(ni & 1) * 2]);
        }
    }

    const int g = lane >> 2, c4 = lane & 3;

    if (MODE == 4) {
        // ---- fused unwindow + residual + LN2 epilogue (N == 192, n0 == 0) ----
        asm volatile("cp.async.wait_group 0;\n");
        __syncthreads();
        float* ssum = (float*)smraw;       // [64][4]
        float* ssq  = ssum + 256;          // [64][4]

        // per-row-slot flat token index + validity
        int rtok[2][2]; bool rval[2][2];
        #pragma unroll
        for (int mi = 0; mi < 2; mi++)
            #pragma unroll
            for (int rr = 0; rr < 2; rr++) {
                int grow = m0 + wm + mi * 16 + g + rr * 8;
                int bw = grow / NTOK, n = grow - bw * NTOK;
                int li = bw >> 6, wdw = bw & 63;
                int wp_i = n / 72, wa_i = (n / 12) % 6, wo_i = n % 12;
                int pl_s  = (((wdw >> 4) * 2 + wp_i) + 1) & 7;
                int lat_o = (((wdw & 15) * 6 + wa_i) + 3) % 96 - 2;
                int lon_s = ((li * 12 + wo_i) + 6) % 180;
                bool valid = (lat_o >= 0) && (lat_o < 91);
                rval[mi][rr] = valid;
                rtok[mi][rr] = valid ? ((pl_s * 91 + lat_o) * 180 + lon_s) : 0;
            }

        // v = acc + projb + x  (stored back into acc); partial row sums
        float psum[2][2] = {{0.f, 0.f}, {0.f, 0.f}};
        float psq[2][2]  = {{0.f, 0.f}, {0.f, 0.f}};
        #pragma unroll
        for (int mi = 0; mi < 2; mi++)
            #pragma unroll
            for (int ni = 0; ni < 6; ni++) {
                int col0 = wn + ni * 8 + 2 * c4;
                float2 bv = *(const float2*)(bias + col0);
                #pragma unroll
                for (int rr = 0; rr < 2; rr++) {
                    if (!rval[mi][rr]) continue;
                    float2 xv = *(const float2*)(X1 + (size_t)rtok[mi][rr] * DIMC + col0);
                    float v0 = acc[mi][ni][rr * 2 + 0] + bv.x + xv.x;
                    float v1 = acc[mi][ni][rr * 2 + 1] + bv.y + xv.y;
                    acc[mi][ni][rr * 2 + 0] = v0;
                    acc[mi][ni][rr * 2 + 1] = v1;
                    psum[mi][rr] += v0 + v1;
                    psq[mi][rr]  += v0 * v0 + v1 * v1;
                }
            }
        // quad reduce over c4 (lanes xor 1, 2)
        #pragma unroll
        for (int o = 1; o <= 2; o <<= 1)
            #pragma unroll
            for (int mi = 0; mi < 2; mi++)
                #pragma unroll
                for (int rr = 0; rr < 2; rr++) {
                    psum[mi][rr] += __shfl_xor_sync(0xffffffffu, psum[mi][rr], o);
                    psq[mi][rr]  += __shfl_xor_sync(0xffffffffu, psq[mi][rr], o);
                }
        if (c4 == 0) {
            #pragma unroll
            for (int mi = 0; mi < 2; mi++)
                #pragma unroll
                for (int rr = 0; rr < 2; rr++) {
                    int rloc = wm + mi * 16 + g + rr * 8;
                    ssum[rloc * 4 + (warp & 3)] = psum[mi][rr];
                    ssq[rloc * 4 + (warp & 3)]  = psq[mi][rr];
                }
        }
        __syncthreads();

        #pragma unroll
        for (int mi = 0; mi < 2; mi++)
            #pragma unroll
            for (int rr = 0; rr < 2; rr++) {
                if (!rval[mi][rr]) continue;
                int rloc = wm + mi * 16 + g + rr * 8;
                float s = ssum[rloc * 4] + ssum[rloc * 4 + 1] + ssum[rloc * 4 + 2] + ssum[rloc * 4 + 3];
                float q = ssq[rloc * 4] + ssq[rloc * 4 + 1] + ssq[rloc * 4 + 2] + ssq[rloc * 4 + 3];
                float mean = s * (1.f / 192.f);
                float var  = q * (1.f / 192.f) - mean * mean;
                float rstd = rsqrtf(var + 1e-5f);
                size_t tb = (size_t)rtok[mi][rr] * DIMC;
                #pragma unroll
                for (int ni = 0; ni < 6; ni++) {
                    int col0 = wn + ni * 8 + 2 * c4;
                    float v0 = acc[mi][ni][rr * 2 + 0];
                    float v1 = acc[mi][ni][rr * 2 + 1];
                    *(float2*)(Out + tb + col0) = make_float2(v0, v1);
                    float2 wv = *(const float2*)(n2w + col0);
                    float2 bv2 = *(const float2*)(n2b + col0);
                    float h0 = (v0 - mean) * rstd * wv.x + bv2.x;
                    float h1 = (v1 - mean) * rstd * wv.y + bv2.y;
                    *(__nv_bfloat162*)(Cb + tb + col0) =
                        __nv_bfloat162(__float2bfloat16(h0), __float2bfloat16(h1));
                }
            }
        return;
    }

    // standard epilogues
    #pragma unroll
    for (int mi = 0; mi < 2; mi++) {
        #pragma unroll
        for (int ni = 0; ni < 6; ni++) {
            int row0 = m0 + wm + mi * 16 + g;
            int col0 = n0 + wn + ni * 8 + 2 * c4;
            float2 bv = *(const float2*)(bias + col0);
            #pragma unroll
            for (int rr = 0; rr < 2; rr++) {
                int row = row0 + rr * 8;
                if (row >= M) continue;
                float v0 = acc[mi][ni][rr * 2 + 0] + bv.x;
                float v1 = acc[mi][ni][rr * 2 + 1] + bv.y;
                size_t off = (size_t)row * N + col0;
                if (MODE == 1) {
                    *(__nv_bfloat162*)(Cb + off) =
                        __nv_bfloat162(__float2bfloat16(v0), __float2bfloat16(v1));
                } else if (MODE == 2) {
                    float g0 = 0.5f * v0 * (1.0f + erff(v0 * 0.70710678118654752f));
                    float g1 = 0.5f * v1 * (1.0f + erff(v1 * 0.70710678118654752f));
                    *(__nv_bfloat162*)(Cb + off) =
                        __nv_bfloat162(__float2bfloat16(g0), __float2bfloat16(g1));
                } else {
                    float2 xv = *(const float2*)(X1 + off);
                    *(float2*)(Out + off) = make_float2(xv.x + v0, xv.y + v1);
                }
            }
        }
    }
}

// ---------------- tensor-core windowed attention, z-split, streamed bias ----------
__global__ __launch_bounds__(288, 1) void attn_kernel() {
    const int head = blockIdx.x;
    const int wdw = blockIdx.y;
    const int li0 = blockIdx.z * LI_PER_BLK;
    const int tid = threadIdx.x;
    const int lane = tid & 31;
    const int warp = tid >> 5;

    extern __shared__ __align__(16) unsigned char smraw[];
    __nv_bfloat16* sbias = (__nv_bfloat16*)(smraw + 2 * STAGEB);
    int* sid0  = (int*)(smraw + 2 * STAGEB + BIASB);
    int* sid14 = sid0 + NTOK;
    uint32_t squ = (uint32_t)__cvta_generic_to_shared(smraw);
    const uint32_t sbias_u = squ + 2 * STAGEB;

    auto load_st = [&](int st, int li) {
        int bw = li * NWIN + wdw;
        const __nv_bfloat16* gb = g_qkv + (size_t)bw * NTOK * (3 * DIMC) + head * HDIM;
        uint32_t sb = squ + st * STAGEB;
        #pragma unroll
        for (int s = 0; s < 6; s++) {
            int c = tid + s * 288;
            int mat = c / 576, rem = c - mat * 576, j = rem >> 2, q16 = rem & 3;
            const void* gp = gb + (size_t)j * (3 * DIMC) + mat * DIMC + q16 * 8;
            cp_async16(sb + (uint32_t)(mat * MATB + j * (APAD * 2) + q16 * 16), gp, true);
        }
    };

    load_st(li0 & 1, li0);
    asm volatile("cp.async.commit_group;\n");

    {
        const unsigned char* gbias =
            (const unsigned char*)(g_biasPre + (size_t)(head * NWIN + wdw) * NTOK * PADB);
        for (int c = tid; c < BIASB / 16; c += 288)
            cp_async16(sbias_u + (uint32_t)(c * 16), gbias + c * 16, true);
        asm volatile("cp.async.commit_group;\n");
    }

    if (tid < NTOK) {
        int n = tid;
        int wp_i = n / 72, wa_i = (n / 12) % 6, wo_i = n % 12;
        int pl_p  = (wdw >> 4) * 2 + wp_i;
        int lat_p = (wdw & 15) * 6 + wa_i;
        int rpl  = pl_p  < 6  ? 0 : (pl_p  < 7  ? 1 : 2);
        int rlat = lat_p < 90 ? 0 : (lat_p < 93 ? 1 : 2);
        int base = (rpl * 3 + rlat) * 3;
        sid0[n]  = base;
        sid14[n] = base + ((168 + wo_i) >= 174 ? 1 : 0);
    }

    const int qrow0 = warp * 16;
    const int g = lane >> 2, c4 = lane & 3;
    const int row0 = qrow0 + g, row1 = row0 + 8;
    const float qscale = 0.17677669529663687f;

    for (int li = li0; li < li0 + LI_PER_BLK; li++) {
        if (li + 1 < li0 + LI_PER_BLK) {
            load_st((li + 1) & 1, li + 1);
            asm volatile("cp.async.commit_group;\n");
            asm volatile("cp.async.wait_group 1;\n");
        } else {
            asm volatile("cp.async.wait_group 0;\n");
        }
        __syncthreads();

        uint32_t sq_b = squ + (li & 1) * STAGEB;
        uint32_t sk_b = sq_b + MATB;
        uint32_t sv_b = sk_b + MATB;
        const int* sregp = (li == 14) ? sid14 : sid0;

        uint32_t aq[2][4];
        #pragma unroll
        for (int kkidx = 0; kkidx < 2; kkidx++) {
            uint32_t addr = sq_b + (uint32_t)((qrow0 + (lane & 15)) * (APAD * 2)
                                              + kkidx * 32 + (lane & 16));
            ldsm4(aq[kkidx], addr);
        }

        float sacc[18][4];
        #pragma unroll
        for (int t = 0; t < 18; t++)
            #pragma unroll
            for (int c = 0; c < 4; c++) sacc[t][c] = 0.f;

        #pragma unroll
        for (int nt = 0; nt < 9; nt++) {
            #pragma unroll
            for (int kkidx = 0; kkidx < 2; kkidx++) {
                uint32_t bk[4];
                uint32_t addr = sk_b +
                    (uint32_t)((nt * 16 + (lane & 7) + ((lane & 16) >> 1)) * (APAD * 2)
                               + kkidx * 32 + (lane & 8) * 2);
                ldsm4(bk, addr);
                mma16816(sacc[2 * nt],     aq[kkidx], &bk[0]);
                mma16816(sacc[2 * nt + 1], aq[kkidx], &bk[2]);
            }
        }

        const int rg0 = sregp[row0], rg1 = sregp[row1];
        #pragma unroll
        for (int t = 0; t < 18; t++) {
            int col = t * 8 + 2 * c4;
            float2 b0 = __bfloat1622float2(*(const __nv_bfloat162*)(sbias + row0 * PADB + col));
            float2 b1 = __bfloat1622float2(*(const __nv_bfloat162*)(sbias + row1 * PADB + col));
            int rc0 = sregp[col], rc1 = sregp[col + 1];
            sacc[t][0] = fmaf(sacc[t][0], qscale, b0.x + (rc0 != rg0 ? -100.f : 0.f));
            sacc[t][1] = fmaf(sacc[t][1], qscale, b0.y + (rc1 != rg0 ? -100.f : 0.f));
            sacc[t][2] = fmaf(sacc[t][2], qscale, b1.x + (rc0 != rg1 ? -100.f : 0.f));
            sacc[t][3] = fmaf(sacc[t][3], qscale, b1.y + (rc1 != rg1 ? -100.f : 0.f));
        }

        float mx0 = -1e30f, mx1 = -1e30f;
        #pragma unroll
        for (int t = 0; t < 18; t++) {
            mx0 = fmaxf(mx0, fmaxf(sacc[t][0], sacc[t][1]));
            mx1 = fmaxf(mx1, fmaxf(sacc[t][2], sacc[t][3]));
        }
        #pragma unroll
        for (int o = 1; o <= 2; o <<= 1) {
            mx0 = fmaxf(mx0, __shfl_xor_sync(0xffffffffu, mx0, o));
            mx1 = fmaxf(mx1, __shfl_xor_sync(0xffffffffu, mx1, o));
        }
        float sum0 = 0.f, sum1 = 0.f;
        #pragma unroll
        for (int t = 0; t < 18; t++) {
            sacc[t][0] = __expf(sacc[t][0] - mx0);
            sacc[t][1] = __expf(sacc[t][1] - mx0);
            sacc[t][2] = __expf(sacc[t][2] - mx1);
            sacc[t][3] = __expf(sacc[t][3] - mx1);
            sum0 += sacc[t][0] + sacc[t][1];
            sum1 += sacc[t][2] + sacc[t][3];
        }
        #pragma unroll
        for (int o = 1; o <= 2; o <<= 1) {
            sum0 += __shfl_xor_sync(0xffffffffu, sum0, o);
            sum1 += __shfl_xor_sync(0xffffffffu, sum1, o);
        }
        float inv0 = 1.f / sum0, inv1 = 1.f / sum1;

        uint32_t ap[9][4];
        #pragma unroll
        for (int kt = 0; kt < 9; kt++) {
            ap[kt][0] = packbf2(sacc[2 * kt][0],     sacc[2 * kt][1]);
            ap[kt][1] = packbf2(sacc[2 * kt][2],     sacc[2 * kt][3]);
            ap[kt][2] = packbf2(sacc[2 * kt + 1][0], sacc[2 * kt + 1][1]);
            ap[kt][3] = packbf2(sacc[2 * kt + 1][2], sacc[2 * kt + 1][3]);
        }

        float oacc[4][4];
        #pragma unroll
        for (int t = 0; t < 4; t++)
            #pragma unroll
            for (int c = 0; c < 4; c++) oacc[t][c] = 0.f;

        #pragma unroll
        for (int kt = 0; kt < 9; kt++) {
            #pragma unroll
            for (int dh = 0; dh < 2; dh++) {
                uint32_t bv[4];
                uint32_t addr = sv_b +
                    (uint32_t)((kt * 16 + (lane & 15)) * (APAD * 2) + dh * 32 + (lane & 16));
                ldsm4t(bv, addr);
                mma16816(oacc[2 * dh],     ap[kt], &bv[0]);
                mma16816(oacc[2 * dh + 1], ap[kt], &bv[2]);
            }
        }

        int bw = li * NWIN + wdw;
        #pragma unroll
        for (int dt = 0; dt < 4; dt++) {
            int col = head * HDIM + dt * 8 + 2 * c4;
            size_t t0 = (size_t)(bw * NTOK + row0) * DIMC + col;
            size_t t1 = (size_t)(bw * NTOK + row1) * DIMC + col;
            *(__nv_bfloat162*)(g_attnout + t0) =
                __nv_bfloat162(__float2bfloat16(oacc[dt][0] * inv0), __float2bfloat16(oacc[dt][1] * inv0));
            *(__nv_bfloat162*)(g_attnout + t1) =
                __nv_bfloat162(__float2bfloat16(oacc[dt][2] * inv1), __float2bfloat16(oacc[dt][3] * inv1));
        }
        __syncthreads();
    }
}

// ---------------- launch ----------------
extern "C" void kernel_launch(void* const* d_in, const int* in_sizes, int n_in,
                              void* d_out, int out_size) {
    const float* x     = (const float*)d_in[0];
    const float* n1w   = (const float*)d_in[1];
    const float* n1b   = (const float*)d_in[2];
    const float* qkvw  = (const float*)d_in[3];
    const float* qkvb  = (const float*)d_in[4];
    const float* btab  = (const float*)d_in[5];
    const float* projw = (const float*)d_in[6];
    const float* projb = (const float*)d_in[7];
    const float* n2w   = (const float*)d_in[8];
    const float* n2b   = (const float*)d_in[9];
    const float* fc1w  = (const float*)d_in[10];
    const float* fc1b  = (const float*)d_in[11];
    const float* fc2w  = (const float*)d_in[12];
    const float* fc2b  = (const float*)d_in[13];
    float* out = (float*)d_out;

    void *pA1, *pqkv, *pattn, *px1, *ph2in, *ph2mid;
    void *pwqkv, *pwproj, *pwfc1, *pwfc2;
    cudaGetSymbolAddress(&pA1, g_A1);
    cudaGetSymbolAddress(&pqkv, g_qkv);
    cudaGetSymbolAddress(&pattn, g_attnout);
    cudaGetSymbolAddress(&px1, g_x1);
    cudaGetSymbolAddress(&ph2in, g_h2in);
    cudaGetSymbolAddress(&ph2mid, g_h2mid);
    cudaGetSymbolAddress(&pwqkv, g_wqkv);
    cudaGetSymbolAddress(&pwproj, g_wproj);
    cudaGetSymbolAddress(&pwfc1, g_wfc1);
    cudaGetSymbolAddress(&pwfc2, g_wfc2);

    cudaFuncSetAttribute(gemm2<1>, cudaFuncAttributeMaxDynamicSharedMemorySize, GEMM_SMEM);
    cudaFuncSetAttribute(gemm2<2>, cudaFuncAttributeMaxDynamicSharedMemorySize, GEMM_SMEM);
    cudaFuncSetAttribute(gemm2<3>, cudaFuncAttributeMaxDynamicSharedMemorySize, GEMM_SMEM);
    cudaFuncSetAttribute(gemm2<4>, cudaFuncAttributeMaxDynamicSharedMemorySize, GEMM_SMEM);
    cudaFuncSetAttribute(attn_kernel, cudaFuncAttributeMaxDynamicSharedMemorySize, ATTN_SMEM);

    // 1: merged weight conversions
    wconv_kernel<<<1728, 256>>>(qkvw, projw, fc1w, fc2w);

    // 2: bias table transpose
    btab_t_kernel<<<(BROWS * NWIN * NHEAD + 255) / 256, 256>>>(btab);

    // 3: bias precompute
    bias_pre_kernel<<<NHEAD * NWIN, 256>>>();

    // 4: LN1 + window partition
    ln1_window_kernel<<<TOKW / 8, 256>>>(x, n1w, n1b);

    // 5: QKV GEMM -> bf16
    gemm2<1><<<dim3(3, TOKW / BM), 256, GEMM_SMEM>>>(TOKW, 3 * DIMC, DIMC,
        (const __nv_bfloat16*)pA1, (const __nv_bfloat16*)pwqkv, qkvb,
        (__nv_bfloat16*)pqkv, nullptr, nullptr, nullptr, nullptr);

    // 6: fused windowed attention (z-split, streamed bias)
    attn_kernel<<<dim3(NHEAD, NWIN, NLON / LI_PER_BLK), 288, ATTN_SMEM>>>();

    // 7: proj GEMM + unwindow + residual + LN2 -> g_x1 (fp32) + g_h2in (bf16)
    gemm2<4><<<dim3(1, TOKW / BM), 256, GEMM_SMEM>>>(TOKW, DIMC, DIMC,
        (const __nv_bfloat16*)pattn, (const __nv_bfloat16*)pwproj, projb,
        (__nv_bfloat16*)ph2in, x, (float*)px1, n2w, n2b);

    // 8: fc1 (+ exact GELU) -> bf16
    gemm2<2><<<dim3(4, (L_TOK + BM - 1) / BM), 256, GEMM_SMEM>>>(L_TOK, HID, DIMC,
        (const __nv_bfloat16*)ph2in, (const __nv_bfloat16*)pwfc1, fc1b,
        (__nv_bfloat16*)ph2mid, nullptr, nullptr, nullptr, nullptr);

    // 9: fc2 + residual -> d_out
    gemm2<3><<<dim3(1, (L_TOK + BM - 1) / BM), 256, GEMM_SMEM>>>(L_TOK, DIMC, HID,
        (const __nv_bfloat16*)ph2mid, (const __nv_bfloat16*)pwfc2, fc2b,
        nullptr, (const float*)px1, out, nullptr, nullptr);
}